// round 14
// baseline (speedup 1.0000x reference)
#include <cuda_runtime.h>

// ---------------------------------------------------------------------------
// PixelEachSubstitutor R14 = R13 (proven 98.7us) + fusion of
// attn@vp + encoder LN1/FFN/LN2 into one phase (OGG + OF9 staging deleted,
// one barrier removed; residual read directly from g_G2).
// ---------------------------------------------------------------------------

#define SCALE_Q 0.30151134457776363f   // 1/sqrt(11)
#define ACT 1360

__device__ float g_y1[320];
__device__ float g_qc[320];
__device__ float g_Ak[352];   // [h*11+p]
__device__ float g_Av[352];
__device__ volatile int g_pre_done = 0;   // monotonic; never reset
__device__ int g_field_cnt = 0;           // monotonic; never reset
__device__ __align__(16) float g_QK[16 * 1024 * 32];  // q(scaled) 0..10, k 16..26
__device__ __align__(16) float g_G2[16 * 1024 * 32];  // vp 0..10, x-raw 16..25, one@26
__device__ __align__(16) float g_E [16 * 1024 * 32];  // exp(q.k) rel slots 0..24

__constant__ int c_cell9[9] = {0, 1, 2, 32, 33, 34, 64, 65, 66};
__constant__ int c_rel144[144] = {
    12,13,14,17,18,19,22,23,24, 0,0,0,0,0,0,0,
    11,12,13,16,17,18,21,22,23, 0,0,0,0,0,0,0,
    10,11,12,15,16,17,20,21,22, 0,0,0,0,0,0,0,
     7, 8, 9,12,13,14,17,18,19, 0,0,0,0,0,0,0,
     6, 7, 8,11,12,13,16,17,18, 0,0,0,0,0,0,0,
     5, 6, 7,10,11,12,15,16,17, 0,0,0,0,0,0,0,
     2, 3, 4, 7, 8, 9,12,13,14, 0,0,0,0,0,0,0,
     1, 2, 3, 6, 7, 8,11,12,13, 0,0,0,0,0,0,0,
     0, 1, 2, 5, 6, 7,10,11,12, 0,0,0,0,0,0,0
};

__device__ __forceinline__ float warp_sum(float v) {
    v += __shfl_xor_sync(0xffffffffu, v, 16);
    v += __shfl_xor_sync(0xffffffffu, v, 8);
    v += __shfl_xor_sync(0xffffffffu, v, 4);
    v += __shfl_xor_sync(0xffffffffu, v, 2);
    v += __shfl_xor_sync(0xffffffffu, v, 1);
    return v;
}
__device__ __forceinline__ float warp_sum16(float v) {
    v += __shfl_xor_sync(0xffffffffu, v, 8);
    v += __shfl_xor_sync(0xffffffffu, v, 4);
    v += __shfl_xor_sync(0xffffffffu, v, 2);
    v += __shfl_xor_sync(0xffffffffu, v, 1);
    return v;
}

// ---------------------------------------------------------------------------
// Prep kernel: 384 blocks x 256 (unchanged).
// ---------------------------------------------------------------------------
__global__ void __launch_bounds__(256) prep_kernel(
    const float* __restrict__ x,
    const float* __restrict__ enc_in,   // (33,11)
    const float* __restrict__ enc_out)  // (11,11)
{
    const int tid = threadIdx.x;

    if (blockIdx.x < 64) {
        __shared__ float sEI[363];
        __shared__ float sM[110], sBvp[11];

        for (int t = tid; t < 363; t += 256) sEI[t] = enc_in[t];
        __syncthreads();
        if (tid < 110) {
            int c = tid / 10, cp = tid % 10;
            float acc = 0.f;
            #pragma unroll
            for (int a = 0; a < 11; a++)
                acc = fmaf(__ldg(enc_out + c * 11 + a), sEI[(22 + a) * 11 + cp], acc);
            sM[tid] = acc;
        }
        if (tid < 11) {
            float acc = 0.f;
            #pragma unroll
            for (int a = 0; a < 11; a++)
                acc = fmaf(__ldg(enc_out + tid * 11 + a), sEI[(22 + a) * 11 + 10], acc);
            sBvp[tid] = acc;
        }
        __syncthreads();

        const int g = blockIdx.x * 256 + tid;        // 16384 total
        const int cell = g & 1023;
        const int n = g >> 10;
        const int jj = cell & 31, ii = cell >> 5;
        const bool interior = (ii >= 1 && ii <= 30 && jj >= 1 && jj <= 30);

        float xv[10];
        const float* xb = x + n * 9000 + (ii - 1) * 30 + (jj - 1);
        #pragma unroll
        for (int c = 0; c < 10; c++) xv[c] = interior ? xb[c * 900] : 0.0f;

        float qk[32], g2[32];
        #pragma unroll
        for (int s = 0; s < 32; s++) { qk[s] = 0.f; g2[s] = 0.f; }

        #pragma unroll
        for (int a = 0; a < 11; a++) {
            float aq = sEI[a * 11 + 10];
            float ak = sEI[(11 + a) * 11 + 10];
            float av = sBvp[a];
            #pragma unroll
            for (int c = 0; c < 10; c++) {
                aq = fmaf(sEI[a * 11 + c], xv[c], aq);
                ak = fmaf(sEI[(11 + a) * 11 + c], xv[c], ak);
                av = fmaf(sM[a * 10 + c], xv[c], av);
            }
            qk[a] = aq * SCALE_Q;
            qk[16 + a] = ak;
            g2[a] = av;
        }
        #pragma unroll
        for (int c = 0; c < 10; c++) g2[16 + c] = xv[c];
        g2[26] = 1.0f;

        float4* dq = (float4*)&g_QK[g << 5];
        float4* dg = (float4*)&g_G2[g << 5];
        #pragma unroll
        for (int u = 0; u < 8; u++) {
            dq[u] = make_float4(qk[4 * u], qk[4 * u + 1], qk[4 * u + 2], qk[4 * u + 3]);
            dg[u] = make_float4(g2[4 * u], g2[4 * u + 1], g2[4 * u + 2], g2[4 * u + 3]);
        }
        __threadfence();
        __syncthreads();
        if (tid == 0) atomicAdd(&g_field_cnt, 1);
    } else {
        // ---------------- E field (gated) ----------------
        if (tid == 0) {
            while (*((volatile int*)&g_field_cnt) < 64) { }
        }
        __syncthreads();
        __threadfence();

        const int eb = blockIdx.x - 64;                          // 0..319
        const int rg = eb >> 6;                                  // 0..4
        const int g  = ((eb & 63) << 8) | tid;                   // 0..16383
        const int cellA = g & 1023;
        const int ii = cellA >> 5, jj = cellA & 31;
        const int nbase = (g >> 10) << 15;

        const int rA = ii + rg - 2;
        if (rA < 0 || rA > 31) return;

        const float4* Q4 = (const float4*)&g_QK[g << 5];
        float4 q0 = Q4[0], q1 = Q4[1], q2 = Q4[2];

        #pragma unroll
        for (int rb = 0; rb < 5; rb++) {
            const int cB = jj + rb - 2;
            if (cB >= 0 && cB <= 31) {
                const float4* K4 = (const float4*)&g_QK[(nbase | (((rA << 5) | cB) << 5)) + 16];
                float4 k0 = K4[0], k1 = K4[1], k2 = K4[2];
                float acc;
                acc = q0.x * k0.x;
                acc = fmaf(q0.y, k0.y, acc);
                acc = fmaf(q0.z, k0.z, acc);
                acc = fmaf(q0.w, k0.w, acc);
                acc = fmaf(q1.x, k1.x, acc);
                acc = fmaf(q1.y, k1.y, acc);
                acc = fmaf(q1.z, k1.z, acc);
                acc = fmaf(q1.w, k1.w, acc);
                acc = fmaf(q2.x, k2.x, acc);
                acc = fmaf(q2.y, k2.y, acc);
                acc = fmaf(q2.z, k2.z, acc);
                acc = fmaf(q2.w, k2.w, acc);
                g_E[(g << 5) | (rg * 5 + rb)] = __expf(acc);
            }
        }
    }
}

// ---------------------------------------------------------------------------
// Main kernel: grid 3601 x 256.
// act layout per pixel: OVP 0(144) OSC 144(144) OF2 288(187,[a*17+i])
//                       OOA 1024(320) OY2 0(330, second half)
// ---------------------------------------------------------------------------
#define OVP 0
#define OSC 144
#define OF2 288
#define OOA 1024
#define OY2 0
// precompute scratch offsets within act[] (block 0 only)
#define P_VF 0
#define P_QS 320
#define P_OS 1280
#define P_RR 1600
#define P_Y1 1920
#define P_SS 2240

__global__ void __launch_bounds__(256, 4) main_kernel(
    const float* __restrict__ el1, const float* __restrict__ el2,
    const float* __restrict__ eln1, const float* __restrict__ eln2,
    const float* __restrict__ ca_out,
    const float* __restrict__ dl1, const float* __restrict__ dl2,
    const float* __restrict__ dln2, const float* __restrict__ dln3,
    const float* __restrict__ wd0, const float* __restrict__ wd1,
    const float* __restrict__ Vf, const float* __restrict__ sa_in,
    const float* __restrict__ sa_out, const float* __restrict__ dec_ln1,
    const float* __restrict__ ca_in, const float* __restrict__ ffv,
    float* __restrict__ out)
{
    __shared__ float sAk[352], sAv[352];
    __shared__ float sWo2[1056];
    __shared__ float sDlin1[32], sDlin2[32], sDln2w[32], sDln3w[32];
    __shared__ float sWd0[264];
    __shared__ float sLin1[11], sLin2[11], sLn1[11], sLn2[11];
    __shared__ __align__(16) float act[4 * ACT];
    __shared__ int spn[4], sppi[4], sppj[4], sppc[4];

    const int tid = threadIdx.x;
    const int lane = tid & 31;
    const int wrp  = tid >> 5;

    if (blockIdx.x == 0) {
        // ---------------- decoder precompute (unchanged) ----------------
        float* ps = act;
        for (int o = tid; o < 320; o += 256) ps[P_VF + o] = Vf[o];
        if (tid < 32) {
            float s = 0.f;
            for (int p = 9; p < 81; p++) s += __ldg(ffv + tid * 81 + p);
            ps[P_SS + tid] = s;
        }
        __syncthreads();

        for (int o = tid; o < 960; o += 256) {
            int w = o / 320, r = o - w * 320;
            int i = r >> 5, h = r & 31;
            const float* W = sa_in + (w * 32 + h) * 32;
            float acc = 0.f;
            #pragma unroll 8
            for (int v = 0; v < 32; v++)
                acc = fmaf(__ldg(W + v), ps[P_VF + i * 32 + v], acc);
            ps[P_QS + o] = acc;
        }
        __syncthreads();

        for (int o = tid; o < 320; o += 256) {
            int h = o & 31;
            float q = ps[P_QS + o];
            float den = 0.f, num = 0.f;
            #pragma unroll
            for (int j = 0; j < 10; j++) {
                float e = __expf(q * ps[P_QS + 320 + j * 32 + h]);
                den += e;
                num = fmaf(e, ps[P_QS + 640 + j * 32 + h], num);
            }
            ps[P_OS + o] = __fdividef(num, den);
        }
        __syncthreads();

        for (int o = tid; o < 320; o += 256) {
            int i = o >> 5, h = o & 31;
            float acc = 0.f;
            #pragma unroll 8
            for (int hh = 0; hh < 32; hh++)
                acc = fmaf(__ldg(sa_out + h * 32 + hh), ps[P_OS + i * 32 + hh], acc);
            ps[P_RR + o] = ps[P_VF + o] + acc;
        }
        __syncthreads();

        for (int r = wrp; r < 10; r += 8) {
            float l = ps[P_RR + r * 32 + lane];
            float mean = warp_sum(l) * (1.0f / 32.0f);
            float d = l - mean;
            float var = warp_sum(d * d) * (1.0f / 32.0f);
            float inv = rsqrtf(var + 1e-5f);
            float yv = d * inv * __ldg(dec_ln1 + lane);
            ps[P_Y1 + r * 32 + lane] = yv;
            g_y1[r * 32 + lane] = yv;
        }
        __syncthreads();

        for (int o = tid; o < 1024; o += 256) {
            if (o < 320) {
                int i = o >> 5, h = o & 31;
                float acc = 0.f;
                #pragma unroll 8
                for (int v = 0; v < 32; v++)
                    acc = fmaf(__ldg(ca_in + h * 32 + v), ps[P_Y1 + i * 32 + v], acc);
                g_qc[o] = acc;
            } else {
                int oo = o - 320;
                int which = oo / 352, rem = oo - which * 352;
                int h = rem / 11, p = rem - h * 11;
                if (which < 2 && p < 10) {
                    const float* W = ca_in + (32 + which * 32 + h) * 32;
                    float acc = 0.f;
                    if (p < 9) {
                        #pragma unroll 8
                        for (int v = 0; v < 32; v++)
                            acc = fmaf(__ldg(W + v), __ldg(ffv + v * 81 + p), acc);
                    } else {
                        #pragma unroll 8
                        for (int v = 0; v < 32; v++)
                            acc = fmaf(__ldg(W + v), ps[P_SS + v], acc);
                    }
                    (which ? g_Av : g_Ak)[h * 11 + p] = acc;
                }
            }
        }
        __threadfence();
        __syncthreads();
        if (tid == 0) g_pre_done = 1;
        return;
    }

    // ---------------- pixel blocks ----------------
    for (int t = tid; t < 1024; t += 256) sWo2[(t >> 5) * 33 + (t & 31)] = ca_out[t];
    if (tid < 32) {
        sDlin1[tid] = dl1[tid]; sDlin2[tid] = dl2[tid];
        sDln2w[tid] = dln2[tid]; sDln3w[tid] = dln3[tid];
    }
    { int t = tid; sWd0[(t >> 5) * 33 + (t & 31)] = wd0[t]; }
    if (tid < 11) {
        sLin1[tid] = el1[tid]; sLin2[tid] = el2[tid];
        sLn1[tid] = eln1[tid]; sLn2[tid] = eln2[tid];
    }
    if (tid < 4) {
        int pixel = (blockIdx.x - 1) * 4 + tid;
        int n = pixel / 900, rem = pixel % 900;
        int pi = rem / 30, pj = rem % 30;
        spn[tid] = n; sppi[tid] = pi; sppj[tid] = pj;
        sppc[tid] = pi * 32 + pj;
    }
    __syncthreads();

    // ---- gather vp from G2 (slots 0..15 only; f9 read later direct) ----
    for (int t = tid; t < 576; t += 256) {
        int px = t / 144, r = t - px * 144;
        int cellIdx = r >> 4, slot = r & 15;
        int base = (spn[px] << 10) | sppc[px];
        act[px * ACT + OVP + r] = g_G2[((base + c_cell9[cellIdx]) << 5) | slot];
    }
    // ---- gather E ----
    for (int t = tid; t < 576; t += 256) {
        int i = t >> 6, px = (t >> 4) & 3, j = t & 15;
        if (j < 9) {
            int base = (spn[px] << 10) | (sppc[px] + c_cell9[i]);
            act[px * ACT + OSC + (i << 4) + j] =
                __ldg(&g_E[(base << 5) | c_rel144[(i << 4) + j]]);
        }
    }
    __syncthreads();

    // ---- FUSED: attn@vp + residual + LN1 + FFN + LN2 -> f2T ----
    {
        int a = lane & 15;
        bool on = (a < 11);
        float w1  = on ? sLn1[a]  : 0.f;
        float w2  = on ? sLn2[a]  : 0.f;
        float wl1 = on ? sLin1[a] : 0.f;
        float wl2 = on ? sLin2[a] : 0.f;
        #pragma unroll
        for (int p = 0; p < 3; p++) {
            int g = p * 16 + (tid >> 4);          // 0..47
            int gc = (g < 40) ? g : 39;           // clamp: keeps shuffles convergent
            int px = gc & 3, i = gc >> 2;
            float* pb = &act[px * ACT];
            float gg;
            if (i < 9) {
                float den = 72.0f, acc = 0.f;
                #pragma unroll
                for (int j = 0; j < 9; j++) {
                    float e = pb[OSC + (i << 4) + j];        // broadcast
                    den += e;
                    acc = fmaf(e, pb[OVP + (j << 4) + a], acc);
                }
                float f9 = 0.f;
                if (on)
                    f9 = __ldg(&g_G2[((unsigned)((spn[px] << 10) | (sppc[px] + c_cell9[i])) << 5) | (16 + a)]);
                gg = fmaf(acc, __fdividef(1.0f, den), f9);
            } else {
                float s = 0.f;
                #pragma unroll
                for (int j = 0; j < 9; j++) s += pb[OVP + (j << 4) + a];
                gg = s * (1.0f / 81.0f);
            }
            if (!on) gg = 0.f;
            float mean = warp_sum16(gg) * (1.0f / 11.0f);
            float d = on ? (gg - mean) : 0.f;
            float var = warp_sum16(d * d) * (1.0f / 11.0f);
            float inv = rsqrtf(var + 1e-5f);
            float l = d * inv * w1;
            float s1 = fmaxf(warp_sum16(l * wl1), 0.0f);
            l = fmaf(s1, wl2, l);
            float mean2 = warp_sum16(l) * (1.0f / 11.0f);
            float d2 = on ? (l - mean2) : 0.f;
            float var2 = warp_sum16(d2 * d2) * (1.0f / 11.0f);
            float inv2 = rsqrtf(var2 + 1e-5f);
            if (on && g < 40) pb[OF2 + a * 17 + i] = d2 * inv2 * w2;
        }
    }
    __syncthreads();

    // ---- spin-gate on precompute, then stage Ak/Av ----
    if (tid == 0) { while (g_pre_done == 0) { } }
    __syncthreads();
    for (int t = tid; t < 352; t += 256) { sAk[t] = g_Ak[t]; sAv[t] = g_Av[t]; }
    __syncthreads();

    // ---- kc/vc + cross-attention FUSED: 4 warps, all in registers ----
    if (wrp < 4) {
        int px = wrp, h = lane;
        float* pb = &act[px * ACT];
        float ak[10], av[10];
        #pragma unroll
        for (int p = 0; p < 10; p++) {
            ak[p] = sAk[h * 11 + p];
            av[p] = sAv[h * 11 + p];
        }
        float kk[11], vv[11];
        #pragma unroll
        for (int c = 0; c < 11; c++) {
            float accK = 0.f, accV = 0.f;
            #pragma unroll
            for (int p = 0; p < 10; p++) {
                float f = pb[OF2 + c * 17 + p];
                accK = fmaf(f, ak[p], accK);
                accV = fmaf(f, av[p], accV);
            }
            kk[c] = accK;
            vv[c] = accV;
        }
        #pragma unroll
        for (int i = 0; i < 10; i++) {
            float q = __ldg(&g_qc[i * 32 + h]);
            float den = 0.f, num = 0.f;
            #pragma unroll
            for (int j = 0; j < 11; j++) {
                float e = __expf(q * kk[j]);
                den += e;
                num = fmaf(e, vv[j], num);
            }
            pb[OOA + i * 32 + h] = __fdividef(num, den);
        }
    }
    __syncthreads();

    // ---- CA out projection + residual (y1 via direct coalesced __ldg) ----
    {
        int c = lane, px = wrp & 3, ih = wrp >> 2;
        float* pb = &act[px * ACT];
        float w[32];
        #pragma unroll
        for (int hh = 0; hh < 32; hh++) w[hh] = sWo2[c * 33 + hh];
        #pragma unroll
        for (int k = 0; k < 5; k++) {
            int i = ih * 5 + k;
            const float4* o4 = (const float4*)&pb[OOA + i * 32];
            float acc = 0.f;
            #pragma unroll
            for (int q4 = 0; q4 < 8; q4++) {
                float4 m4 = o4[q4];
                acc = fmaf(w[4 * q4 + 0], m4.x, acc);
                acc = fmaf(w[4 * q4 + 1], m4.y, acc);
                acc = fmaf(w[4 * q4 + 2], m4.z, acc);
                acc = fmaf(w[4 * q4 + 3], m4.w, acc);
            }
            pb[OY2 + i * 33 + c] = __ldg(&g_y1[i * 32 + c]) + acc;
        }
    }
    __syncthreads();

    // ---- decoder LN2 + FFN + LN3 ----
    {
        float w2  = sDln2w[lane];
        float w3  = sDln3w[lane];
        float wl1 = sDlin1[lane];
        float wl2 = sDlin2[lane];
        for (int r = wrp; r < 40; r += 8) {
            int px = r & 3, i = r >> 2;
            float* row = &act[px * ACT + OY2 + i * 33];
            float l = row[lane];
            float mean = warp_sum(l) * (1.0f / 32.0f);
            float d = l - mean;
            float var = warp_sum(d * d) * (1.0f / 32.0f);
            float inv = rsqrtf(var + 1e-5f);
            l = d * inv * w2;
            float s1 = fmaxf(warp_sum(l * wl1), 0.0f);
            l = fmaf(s1, wl2, l);
            float mean2 = warp_sum(l) * (1.0f / 32.0f);
            float d2 = l - mean2;
            float var2 = warp_sum(d2 * d2) * (1.0f / 32.0f);
            float inv2 = rsqrtf(var2 + 1e-5f);
            row[lane] = d2 * inv2 * w3;
        }
    }
    __syncthreads();

    // ---- head: warp per (px, class); direct-to-gmem ----
    {
        int k = lane >> 2, cq = lane & 3;
        #pragma unroll
        for (int it = 0; it < 5; it++) {
            int pair = wrp + 8 * it;          // 0..39
            int px = pair & 3, i = pair >> 2; // i = class 0..9
            float* pb = &act[px * ACT];
            float partial = 0.f;
            #pragma unroll
            for (int u = 0; u < 8; u++)
                partial = fmaf(sWd0[k * 33 + cq * 8 + u],
                               pb[OY2 + i * 33 + cq * 8 + u], partial);
            partial += __shfl_xor_sync(0xffffffffu, partial, 1);
            partial += __shfl_xor_sync(0xffffffffu, partial, 2);
            float hk = fmaxf(partial, 0.0f) * __ldg(wd1 + k);
            hk += __shfl_xor_sync(0xffffffffu, hk, 4);
            hk += __shfl_xor_sync(0xffffffffu, hk, 8);
            hk += __shfl_xor_sync(0xffffffffu, hk, 16);
            if (lane == 0)
                out[((spn[px] * 10 + i) * 30 + sppi[px]) * 30 + sppj[px]] = hk;
        }
    }
}

extern "C" void kernel_launch(void* const* d_in, const int* in_sizes, int n_in,
                              void* d_out, int out_size) {
    const float* x       = (const float*)d_in[0];
    const float* Vf      = (const float*)d_in[1];
    const float* enc_in  = (const float*)d_in[2];
    const float* enc_out = (const float*)d_in[3];
    const float* el1     = (const float*)d_in[4];
    const float* el2     = (const float*)d_in[5];
    const float* eln1    = (const float*)d_in[6];
    const float* eln2    = (const float*)d_in[7];
    const float* ffv     = (const float*)d_in[8];
    const float* sa_in   = (const float*)d_in[9];
    const float* sa_out  = (const float*)d_in[10];
    const float* ca_in   = (const float*)d_in[11];
    const float* ca_out  = (const float*)d_in[12];
    const float* dl1     = (const float*)d_in[13];
    const float* dl2     = (const float*)d_in[14];
    const float* dln1    = (const float*)d_in[15];
    const float* dln2    = (const float*)d_in[16];
    const float* dln3    = (const float*)d_in[17];
    const float* wd0     = (const float*)d_in[18];
    const float* wd1     = (const float*)d_in[19];

    prep_kernel<<<384, 256>>>(x, enc_in, enc_out);
    main_kernel<<<3601, 256>>>(el1, el2, eln1, eln2, ca_out,
                               dl1, dl2, dln2, dln3, wd0, wd1,
                               Vf, sa_in, sa_out, dln1, ca_in, ffv,
                               (float*)d_out);
}

// round 15
// speedup vs baseline: 1.0463x; 1.0463x over previous
#include <cuda_runtime.h>

// ---------------------------------------------------------------------------
// PixelEachSubstitutor R15 = R13 (proven 98.7us) with __launch_bounds__(256,5)
// on the main kernel: trade ~13 register spills (cold, phase-boundary) for
// 5 blocks/SM occupancy (47.8% -> ~59%).
// ---------------------------------------------------------------------------

#define SCALE_Q 0.30151134457776363f   // 1/sqrt(11)
#define ACT 1360

__device__ float g_y1[320];
__device__ float g_qc[320];
__device__ float g_Ak[352];   // [h*11+p]
__device__ float g_Av[352];
__device__ volatile int g_pre_done = 0;   // monotonic; never reset
__device__ int g_field_cnt = 0;           // monotonic; never reset
__device__ __align__(16) float g_QK[16 * 1024 * 32];  // q(scaled) 0..10, k 16..26
__device__ __align__(16) float g_G2[16 * 1024 * 32];  // vp 0..10, x-raw 16..25, one@26
__device__ __align__(16) float g_E [16 * 1024 * 32];  // exp(q.k) rel slots 0..24

__constant__ int c_cell9[9] = {0, 1, 2, 32, 33, 34, 64, 65, 66};
__constant__ int c_rel144[144] = {
    12,13,14,17,18,19,22,23,24, 0,0,0,0,0,0,0,
    11,12,13,16,17,18,21,22,23, 0,0,0,0,0,0,0,
    10,11,12,15,16,17,20,21,22, 0,0,0,0,0,0,0,
     7, 8, 9,12,13,14,17,18,19, 0,0,0,0,0,0,0,
     6, 7, 8,11,12,13,16,17,18, 0,0,0,0,0,0,0,
     5, 6, 7,10,11,12,15,16,17, 0,0,0,0,0,0,0,
     2, 3, 4, 7, 8, 9,12,13,14, 0,0,0,0,0,0,0,
     1, 2, 3, 6, 7, 8,11,12,13, 0,0,0,0,0,0,0,
     0, 1, 2, 5, 6, 7,10,11,12, 0,0,0,0,0,0,0
};

__device__ __forceinline__ float warp_sum(float v) {
    v += __shfl_xor_sync(0xffffffffu, v, 16);
    v += __shfl_xor_sync(0xffffffffu, v, 8);
    v += __shfl_xor_sync(0xffffffffu, v, 4);
    v += __shfl_xor_sync(0xffffffffu, v, 2);
    v += __shfl_xor_sync(0xffffffffu, v, 1);
    return v;
}
__device__ __forceinline__ float warp_sum16(float v) {
    v += __shfl_xor_sync(0xffffffffu, v, 8);
    v += __shfl_xor_sync(0xffffffffu, v, 4);
    v += __shfl_xor_sync(0xffffffffu, v, 2);
    v += __shfl_xor_sync(0xffffffffu, v, 1);
    return v;
}

// ---------------------------------------------------------------------------
// Prep kernel: 384 blocks x 256 (unchanged).
// ---------------------------------------------------------------------------
__global__ void __launch_bounds__(256) prep_kernel(
    const float* __restrict__ x,
    const float* __restrict__ enc_in,   // (33,11)
    const float* __restrict__ enc_out)  // (11,11)
{
    const int tid = threadIdx.x;

    if (blockIdx.x < 64) {
        __shared__ float sEI[363];
        __shared__ float sM[110], sBvp[11];

        for (int t = tid; t < 363; t += 256) sEI[t] = enc_in[t];
        __syncthreads();
        if (tid < 110) {
            int c = tid / 10, cp = tid % 10;
            float acc = 0.f;
            #pragma unroll
            for (int a = 0; a < 11; a++)
                acc = fmaf(__ldg(enc_out + c * 11 + a), sEI[(22 + a) * 11 + cp], acc);
            sM[tid] = acc;
        }
        if (tid < 11) {
            float acc = 0.f;
            #pragma unroll
            for (int a = 0; a < 11; a++)
                acc = fmaf(__ldg(enc_out + tid * 11 + a), sEI[(22 + a) * 11 + 10], acc);
            sBvp[tid] = acc;
        }
        __syncthreads();

        const int g = blockIdx.x * 256 + tid;        // 16384 total
        const int cell = g & 1023;
        const int n = g >> 10;
        const int jj = cell & 31, ii = cell >> 5;
        const bool interior = (ii >= 1 && ii <= 30 && jj >= 1 && jj <= 30);

        float xv[10];
        const float* xb = x + n * 9000 + (ii - 1) * 30 + (jj - 1);
        #pragma unroll
        for (int c = 0; c < 10; c++) xv[c] = interior ? xb[c * 900] : 0.0f;

        float qk[32], g2[32];
        #pragma unroll
        for (int s = 0; s < 32; s++) { qk[s] = 0.f; g2[s] = 0.f; }

        #pragma unroll
        for (int a = 0; a < 11; a++) {
            float aq = sEI[a * 11 + 10];
            float ak = sEI[(11 + a) * 11 + 10];
            float av = sBvp[a];
            #pragma unroll
            for (int c = 0; c < 10; c++) {
                aq = fmaf(sEI[a * 11 + c], xv[c], aq);
                ak = fmaf(sEI[(11 + a) * 11 + c], xv[c], ak);
                av = fmaf(sM[a * 10 + c], xv[c], av);
            }
            qk[a] = aq * SCALE_Q;
            qk[16 + a] = ak;
            g2[a] = av;
        }
        #pragma unroll
        for (int c = 0; c < 10; c++) g2[16 + c] = xv[c];
        g2[26] = 1.0f;

        float4* dq = (float4*)&g_QK[g << 5];
        float4* dg = (float4*)&g_G2[g << 5];
        #pragma unroll
        for (int u = 0; u < 8; u++) {
            dq[u] = make_float4(qk[4 * u], qk[4 * u + 1], qk[4 * u + 2], qk[4 * u + 3]);
            dg[u] = make_float4(g2[4 * u], g2[4 * u + 1], g2[4 * u + 2], g2[4 * u + 3]);
        }
        __threadfence();
        __syncthreads();
        if (tid == 0) atomicAdd(&g_field_cnt, 1);
    } else {
        // ---------------- E field (gated) ----------------
        if (tid == 0) {
            while (*((volatile int*)&g_field_cnt) < 64) { }
        }
        __syncthreads();
        __threadfence();

        const int eb = blockIdx.x - 64;                          // 0..319
        const int rg = eb >> 6;                                  // 0..4
        const int g  = ((eb & 63) << 8) | tid;                   // 0..16383
        const int cellA = g & 1023;
        const int ii = cellA >> 5, jj = cellA & 31;
        const int nbase = (g >> 10) << 15;

        const int rA = ii + rg - 2;
        if (rA < 0 || rA > 31) return;

        const float4* Q4 = (const float4*)&g_QK[g << 5];
        float4 q0 = Q4[0], q1 = Q4[1], q2 = Q4[2];

        #pragma unroll
        for (int rb = 0; rb < 5; rb++) {
            const int cB = jj + rb - 2;
            if (cB >= 0 && cB <= 31) {
                const float4* K4 = (const float4*)&g_QK[(nbase | (((rA << 5) | cB) << 5)) + 16];
                float4 k0 = K4[0], k1 = K4[1], k2 = K4[2];
                float acc;
                acc = q0.x * k0.x;
                acc = fmaf(q0.y, k0.y, acc);
                acc = fmaf(q0.z, k0.z, acc);
                acc = fmaf(q0.w, k0.w, acc);
                acc = fmaf(q1.x, k1.x, acc);
                acc = fmaf(q1.y, k1.y, acc);
                acc = fmaf(q1.z, k1.z, acc);
                acc = fmaf(q1.w, k1.w, acc);
                acc = fmaf(q2.x, k2.x, acc);
                acc = fmaf(q2.y, k2.y, acc);
                acc = fmaf(q2.z, k2.z, acc);
                acc = fmaf(q2.w, k2.w, acc);
                g_E[(g << 5) | (rg * 5 + rb)] = __expf(acc);
            }
        }
    }
}

// ---------------------------------------------------------------------------
// Main kernel: grid 3601 x 256.
// ---------------------------------------------------------------------------
#define OSC 0
#define OVP 144
#define OF9 288
#define OGG 448
#define OF2 0
#define OOA 1024
#define OY2 0
// precompute scratch offsets within act[] (block 0 only)
#define P_VF 0
#define P_QS 320
#define P_OS 1280
#define P_RR 1600
#define P_Y1 1920
#define P_SS 2240

__global__ void __launch_bounds__(256, 5) main_kernel(
    const float* __restrict__ el1, const float* __restrict__ el2,
    const float* __restrict__ eln1, const float* __restrict__ eln2,
    const float* __restrict__ ca_out,
    const float* __restrict__ dl1, const float* __restrict__ dl2,
    const float* __restrict__ dln2, const float* __restrict__ dln3,
    const float* __restrict__ wd0, const float* __restrict__ wd1,
    const float* __restrict__ Vf, const float* __restrict__ sa_in,
    const float* __restrict__ sa_out, const float* __restrict__ dec_ln1,
    const float* __restrict__ ca_in, const float* __restrict__ ffv,
    float* __restrict__ out)
{
    __shared__ float sAk[352], sAv[352];
    __shared__ float sWo2[1056];
    __shared__ float sDlin1[32], sDlin2[32], sDln2w[32], sDln3w[32];
    __shared__ float sWd0[264];
    __shared__ float sLin1[11], sLin2[11], sLn1[11], sLn2[11];
    __shared__ __align__(16) float act[4 * ACT];
    __shared__ int spn[4], sppi[4], sppj[4], sppc[4];

    const int tid = threadIdx.x;
    const int lane = tid & 31;
    const int wrp  = tid >> 5;

    if (blockIdx.x == 0) {
        // ---------------- decoder precompute (unchanged) ----------------
        float* ps = act;
        for (int o = tid; o < 320; o += 256) ps[P_VF + o] = Vf[o];
        if (tid < 32) {
            float s = 0.f;
            for (int p = 9; p < 81; p++) s += __ldg(ffv + tid * 81 + p);
            ps[P_SS + tid] = s;
        }
        __syncthreads();

        for (int o = tid; o < 960; o += 256) {
            int w = o / 320, r = o - w * 320;
            int i = r >> 5, h = r & 31;
            const float* W = sa_in + (w * 32 + h) * 32;
            float acc = 0.f;
            #pragma unroll 8
            for (int v = 0; v < 32; v++)
                acc = fmaf(__ldg(W + v), ps[P_VF + i * 32 + v], acc);
            ps[P_QS + o] = acc;
        }
        __syncthreads();

        for (int o = tid; o < 320; o += 256) {
            int h = o & 31;
            float q = ps[P_QS + o];
            float den = 0.f, num = 0.f;
            #pragma unroll
            for (int j = 0; j < 10; j++) {
                float e = __expf(q * ps[P_QS + 320 + j * 32 + h]);
                den += e;
                num = fmaf(e, ps[P_QS + 640 + j * 32 + h], num);
            }
            ps[P_OS + o] = __fdividef(num, den);
        }
        __syncthreads();

        for (int o = tid; o < 320; o += 256) {
            int i = o >> 5, h = o & 31;
            float acc = 0.f;
            #pragma unroll 8
            for (int hh = 0; hh < 32; hh++)
                acc = fmaf(__ldg(sa_out + h * 32 + hh), ps[P_OS + i * 32 + hh], acc);
            ps[P_RR + o] = ps[P_VF + o] + acc;
        }
        __syncthreads();

        for (int r = wrp; r < 10; r += 8) {
            float l = ps[P_RR + r * 32 + lane];
            float mean = warp_sum(l) * (1.0f / 32.0f);
            float d = l - mean;
            float var = warp_sum(d * d) * (1.0f / 32.0f);
            float inv = rsqrtf(var + 1e-5f);
            float yv = d * inv * __ldg(dec_ln1 + lane);
            ps[P_Y1 + r * 32 + lane] = yv;
            g_y1[r * 32 + lane] = yv;
        }
        __syncthreads();

        for (int o = tid; o < 1024; o += 256) {
            if (o < 320) {
                int i = o >> 5, h = o & 31;
                float acc = 0.f;
                #pragma unroll 8
                for (int v = 0; v < 32; v++)
                    acc = fmaf(__ldg(ca_in + h * 32 + v), ps[P_Y1 + i * 32 + v], acc);
                g_qc[o] = acc;
            } else {
                int oo = o - 320;
                int which = oo / 352, rem = oo - which * 352;
                int h = rem / 11, p = rem - h * 11;
                if (which < 2 && p < 10) {
                    const float* W = ca_in + (32 + which * 32 + h) * 32;
                    float acc = 0.f;
                    if (p < 9) {
                        #pragma unroll 8
                        for (int v = 0; v < 32; v++)
                            acc = fmaf(__ldg(W + v), __ldg(ffv + v * 81 + p), acc);
                    } else {
                        #pragma unroll 8
                        for (int v = 0; v < 32; v++)
                            acc = fmaf(__ldg(W + v), ps[P_SS + v], acc);
                    }
                    (which ? g_Av : g_Ak)[h * 11 + p] = acc;
                }
            }
        }
        __threadfence();
        __syncthreads();
        if (tid == 0) g_pre_done = 1;
        return;
    }

    // ---------------- pixel blocks ----------------
    for (int t = tid; t < 1024; t += 256) sWo2[(t >> 5) * 33 + (t & 31)] = ca_out[t];
    if (tid < 32) {
        sDlin1[tid] = dl1[tid]; sDlin2[tid] = dl2[tid];
        sDln2w[tid] = dln2[tid]; sDln3w[tid] = dln3[tid];
    }
    { int t = tid; sWd0[(t >> 5) * 33 + (t & 31)] = wd0[t]; }
    if (tid < 11) {
        sLin1[tid] = el1[tid]; sLin2[tid] = el2[tid];
        sLn1[tid] = eln1[tid]; sLn2[tid] = eln2[tid];
    }
    if (tid < 4) {
        int pixel = (blockIdx.x - 1) * 4 + tid;
        int n = pixel / 900, rem = pixel % 900;
        int pi = rem / 30, pj = rem % 30;
        spn[tid] = n; sppi[tid] = pi; sppj[tid] = pj;
        sppc[tid] = pi * 32 + pj;
    }
    __syncthreads();

    // ---- gather vp + f9 from G2 ----
    {
        int px = tid >> 6, t64 = tid & 63;
        int base = (spn[px] << 10) | sppc[px];
        float* pb = &act[px * ACT];
        #pragma unroll
        for (int it = 0; it < 5; it++) {
            int r = it * 64 + t64;
            if (r < 288) {
                int cellIdx = r >> 5, slot = r & 31;
                float v = g_G2[((base + c_cell9[cellIdx]) << 5) | slot];
                pb[OVP + (slot >> 4) * 144 + (cellIdx << 4) + (slot & 15)] = v;
            }
        }
    }
    // ---- gather E ----
    for (int t = tid; t < 576; t += 256) {
        int i = t >> 6, px = (t >> 4) & 3, j = t & 15;
        if (j < 9) {
            int base = (spn[px] << 10) | (sppc[px] + c_cell9[i]);
            act[px * ACT + OSC + (i << 4) + j] =
                __ldg(&g_E[(base << 5) | c_rel144[(i << 4) + j]]);
        }
    }
    __syncthreads();

    // ---- attn @ vp + residual; denominators fused in ----
    for (int t = tid; t < 640; t += 256) {
        int i = t >> 6, px = (t >> 4) & 3, a = t & 15;
        if (a < 11) {
            float* pb = &act[px * ACT];
            if (i < 9) {
                float den = 72.0f, acc = 0.f;
                #pragma unroll
                for (int j = 0; j < 9; j++) {
                    float e = pb[OSC + (i << 4) + j];
                    den += e;
                    acc = fmaf(e, pb[OVP + (j << 4) + a], acc);
                }
                float inv = __fdividef(1.0f, den);
                pb[OGG + (i << 4) + a] = fmaf(acc, inv, pb[OF9 + (i << 4) + a]);
            } else {
                float s = 0.f;
                #pragma unroll
                for (int j = 0; j < 9; j++) s += pb[OVP + (j << 4) + a];
                pb[OGG + 144 + a] = s * (1.0f / 81.0f);
            }
        }
    }
    __syncthreads();

    // ---- encoder LN1 + FFN + LN2 -> f2T ----
    {
        int c = lane & 15;
        bool on = (c < 11);
        float w1  = on ? sLn1[c]  : 0.f;
        float w2  = on ? sLn2[c]  : 0.f;
        float wl1 = on ? sLin1[c] : 0.f;
        float wl2 = on ? sLin2[c] : 0.f;
        for (int rp = wrp; rp < 20; rp += 8) {
            int px = rp / 5, pr = rp % 5;
            int row = pr * 2 + (lane >> 4);
            float* pb = &act[px * ACT];
            float l = on ? pb[OGG + (row << 4) + c] : 0.f;
            float mean = warp_sum16(l) * (1.0f / 11.0f);
            float d = on ? (l - mean) : 0.f;
            float var = warp_sum16(d * d) * (1.0f / 11.0f);
            float inv = rsqrtf(var + 1e-5f);
            l = d * inv * w1;
            float s1 = fmaxf(warp_sum16(l * wl1), 0.0f);
            l = fmaf(s1, wl2, l);
            float mean2 = warp_sum16(l) * (1.0f / 11.0f);
            float d2 = on ? (l - mean2) : 0.f;
            float var2 = warp_sum16(d2 * d2) * (1.0f / 11.0f);
            float inv2 = rsqrtf(var2 + 1e-5f);
            if (on) pb[OF2 + c * 17 + row] = d2 * inv2 * w2;
        }
    }
    __syncthreads();

    // ---- spin-gate on precompute, then stage Ak/Av ----
    if (tid == 0) { while (g_pre_done == 0) { } }
    __syncthreads();
    for (int t = tid; t < 352; t += 256) { sAk[t] = g_Ak[t]; sAv[t] = g_Av[t]; }
    __syncthreads();

    // ---- kc/vc + cross-attention FUSED: 4 warps, all in registers ----
    if (wrp < 4) {
        int px = wrp, h = lane;
        float* pb = &act[px * ACT];
        float ak[10], av[10];
        #pragma unroll
        for (int p = 0; p < 10; p++) {
            ak[p] = sAk[h * 11 + p];
            av[p] = sAv[h * 11 + p];
        }
        float kk[11], vv[11];
        #pragma unroll
        for (int c = 0; c < 11; c++) {
            float accK = 0.f, accV = 0.f;
            #pragma unroll
            for (int p = 0; p < 10; p++) {
                float f = pb[OF2 + c * 17 + p];
                accK = fmaf(f, ak[p], accK);
                accV = fmaf(f, av[p], accV);
            }
            kk[c] = accK;
            vv[c] = accV;
        }
        #pragma unroll
        for (int i = 0; i < 10; i++) {
            float q = __ldg(&g_qc[i * 32 + h]);
            float den = 0.f, num = 0.f;
            #pragma unroll
            for (int j = 0; j < 11; j++) {
                float e = __expf(q * kk[j]);
                den += e;
                num = fmaf(e, vv[j], num);
            }
            pb[OOA + i * 32 + h] = __fdividef(num, den);
        }
    }
    __syncthreads();

    // ---- CA out projection + residual (y1 via direct coalesced __ldg) ----
    {
        int c = lane, px = wrp & 3, ih = wrp >> 2;
        float* pb = &act[px * ACT];
        float w[32];
        #pragma unroll
        for (int hh = 0; hh < 32; hh++) w[hh] = sWo2[c * 33 + hh];
        #pragma unroll
        for (int k = 0; k < 5; k++) {
            int i = ih * 5 + k;
            const float4* o4 = (const float4*)&pb[OOA + i * 32];
            float acc = 0.f;
            #pragma unroll
            for (int q4 = 0; q4 < 8; q4++) {
                float4 m4 = o4[q4];
                acc = fmaf(w[4 * q4 + 0], m4.x, acc);
                acc = fmaf(w[4 * q4 + 1], m4.y, acc);
                acc = fmaf(w[4 * q4 + 2], m4.z, acc);
                acc = fmaf(w[4 * q4 + 3], m4.w, acc);
            }
            pb[OY2 + i * 33 + c] = __ldg(&g_y1[i * 32 + c]) + acc;
        }
    }
    __syncthreads();

    // ---- decoder LN2 + FFN + LN3 ----
    {
        float w2  = sDln2w[lane];
        float w3  = sDln3w[lane];
        float wl1 = sDlin1[lane];
        float wl2 = sDlin2[lane];
        for (int r = wrp; r < 40; r += 8) {
            int px = r & 3, i = r >> 2;
            float* row = &act[px * ACT + OY2 + i * 33];
            float l = row[lane];
            float mean = warp_sum(l) * (1.0f / 32.0f);
            float d = l - mean;
            float var = warp_sum(d * d) * (1.0f / 32.0f);
            float inv = rsqrtf(var + 1e-5f);
            l = d * inv * w2;
            float s1 = fmaxf(warp_sum(l * wl1), 0.0f);
            l = fmaf(s1, wl2, l);
            float mean2 = warp_sum(l) * (1.0f / 32.0f);
            float d2 = l - mean2;
            float var2 = warp_sum(d2 * d2) * (1.0f / 32.0f);
            float inv2 = rsqrtf(var2 + 1e-5f);
            row[lane] = d2 * inv2 * w3;
        }
    }
    __syncthreads();

    // ---- head: warp per (px, class); direct-to-gmem ----
    {
        int k = lane >> 2, cq = lane & 3;
        #pragma unroll
        for (int it = 0; it < 5; it++) {
            int pair = wrp + 8 * it;          // 0..39
            int px = pair & 3, i = pair >> 2; // i = class 0..9
            float* pb = &act[px * ACT];
            float partial = 0.f;
            #pragma unroll
            for (int u = 0; u < 8; u++)
                partial = fmaf(sWd0[k * 33 + cq * 8 + u],
                               pb[OY2 + i * 33 + cq * 8 + u], partial);
            partial += __shfl_xor_sync(0xffffffffu, partial, 1);
            partial += __shfl_xor_sync(0xffffffffu, partial, 2);
            float hk = fmaxf(partial, 0.0f) * __ldg(wd1 + k);
            hk += __shfl_xor_sync(0xffffffffu, hk, 4);
            hk += __shfl_xor_sync(0xffffffffu, hk, 8);
            hk += __shfl_xor_sync(0xffffffffu, hk, 16);
            if (lane == 0)
                out[((spn[px] * 10 + i) * 30 + sppi[px]) * 30 + sppj[px]] = hk;
        }
    }
}

extern "C" void kernel_launch(void* const* d_in, const int* in_sizes, int n_in,
                              void* d_out, int out_size) {
    const float* x       = (const float*)d_in[0];
    const float* Vf      = (const float*)d_in[1];
    const float* enc_in  = (const float*)d_in[2];
    const float* enc_out = (const float*)d_in[3];
    const float* el1     = (const float*)d_in[4];
    const float* el2     = (const float*)d_in[5];
    const float* eln1    = (const float*)d_in[6];
    const float* eln2    = (const float*)d_in[7];
    const float* ffv     = (const float*)d_in[8];
    const float* sa_in   = (const float*)d_in[9];
    const float* sa_out  = (const float*)d_in[10];
    const float* ca_in   = (const float*)d_in[11];
    const float* ca_out  = (const float*)d_in[12];
    const float* dl1     = (const float*)d_in[13];
    const float* dl2     = (const float*)d_in[14];
    const float* dln1    = (const float*)d_in[15];
    const float* dln2    = (const float*)d_in[16];
    const float* dln3    = (const float*)d_in[17];
    const float* wd0     = (const float*)d_in[18];
    const float* wd1     = (const float*)d_in[19];

    prep_kernel<<<384, 256>>>(x, enc_in, enc_out);
    main_kernel<<<3601, 256>>>(el1, el2, eln1, eln2, ca_out,
                               dl1, dl2, dln2, dln3, wd0, wd1,
                               Vf, sa_in, sa_out, dln1, ca_in, ffv,
                               (float*)d_out);
}